// round 15
// baseline (speedup 1.0000x reference)
#include <cuda_runtime.h>
#include <cuda_fp16.h>
#include <cstdint>

// Shape: inp:[2048,2048,3] f32, w_ih:[96,3], w_hh:[96,32], bias:[96], bias_n:[32]
// out:[2048,2048,1] f32 (h[0] each step)
#define TT 2048
#define BB 2048

__device__ __forceinline__ float tanh_hw(float x) {
    float y; asm("tanh.approx.f32 %0, %1;" : "=f"(y) : "f"(x));
    return y;
}

// One warp per sequence; lane j owns hidden unit j.
// Runtime == total fma-pipe cycles (validated R12-R14). All hidden matvecs
// are HFMA2 (96 cyc/step). This round the r/z INPUT gates also go fp16,
// computed for TWO steps per 3 HFMA2 from transposed half-precision x-planes,
// and are seeded directly into the r/z accumulators (their gate-sum FADDs
// vanish). The candidate path stays fp32 end-to-end: ia scalar FFMA from the
// fp32 xbuf, carried h fp32 in registers. r/z weights pre-scaled by 0.5
// (sigmoid fold).
__global__ void __launch_bounds__(32, 14)
gru_warp_kernel(const float* __restrict__ inp,
                const float* __restrict__ w_ih,
                const float* __restrict__ w_hh,
                const float* __restrict__ bias,
                const float* __restrict__ bias_n,
                float* __restrict__ out) {
    __shared__ __align__(16) __half hh[2][32];   // fp16 h broadcast buffer
    __shared__ float  xbuf[96];                  // fp32 x (a-gate only)
    __shared__ __align__(4) __half xh[3][32];    // fp16 x planes [dim][step]

    const int j = threadIdx.x;
    const int b = blockIdx.x;

    // ---- W_hh rows as f16x2 pairs; r/z rows PRE-SCALED by 0.5 ----
    __half2 wr16[16], wz16[16], wa16[16];
    {
        const float* rr = w_hh + (0 * 32 + j) * 32;
        const float* rz = w_hh + (1 * 32 + j) * 32;
        const float* ra = w_hh + (2 * 32 + j) * 32;
#pragma unroll
        for (int k = 0; k < 16; k++) {
            wr16[k] = __floats2half2_rn(0.5f * rr[2 * k], 0.5f * rr[2 * k + 1]);
            wz16[k] = __floats2half2_rn(0.5f * rz[2 * k], 0.5f * rz[2 * k + 1]);
            wa16[k] = __floats2half2_rn(ra[2 * k], ra[2 * k + 1]);
        }
    }
    // r/z W_ih rows + biases as step-duplicated half2, pre-scaled by 0.5.
    __half2 wirh[3], wizh[3];
#pragma unroll
    for (int d = 0; d < 3; d++) {
        const float vr = 0.5f * w_ih[(0 * 32 + j) * 3 + d];
        const float vz = 0.5f * w_ih[(1 * 32 + j) * 3 + d];
        wirh[d] = __float2half2_rn(vr);
        wizh[d] = __float2half2_rn(vz);
    }
    const __half2 brh2 = __float2half2_rn(0.5f * bias[0 * 32 + j]);
    const __half2 bzh2 = __float2half2_rn(0.5f * bias[1 * 32 + j]);
    // a-gate input path stays fp32.
    const float wia0 = w_ih[(2 * 32 + j) * 3 + 0];
    const float wia1 = w_ih[(2 * 32 + j) * 3 + 1];
    const float wia2 = w_ih[(2 * 32 + j) * 3 + 2];
    const float ban  = bias[2 * 32 + j] + bias_n[j];
    const __half hz0 = __float2half(0.0f);

    float h = 0.0f;
    const float* gx   = inp + (size_t)b * (TT * 3);
    float*       gout = out + (size_t)b * TT;

    float p0 = gx[j], p1 = gx[32 + j], p2 = gx[64 + j];

    // One GRU step. IGH = half2 of (ir, iz) seeds for this step (already
    // includes bias and 0.5 prescale); XO = fp32 xbuf offset for ia.
#define GRU_STEP(SLOT, XO, GOFF, IRH, IZH)                                   \
    {                                                                        \
        hh[SLOT][j] = __float2half(h);                                       \
        __syncwarp();                                                        \
        const float x0 = xbuf[(XO) + 0];                                     \
        const float x1 = xbuf[(XO) + 1];                                     \
        const float x2 = xbuf[(XO) + 2];                                     \
        const float ia = fmaf(wia2, x2, fmaf(wia1, x1, fmaf(wia0, x0, ban))); \
        __half2 accr2 = __halves2half2(IRH, hz0);  /* seed = input gate */   \
        __half2 accz2 = __halves2half2(IZH, hz0);                            \
        __half2 acca2a = __float2half2_rn(0.0f);                             \
        __half2 acca2b = __float2half2_rn(0.0f);                             \
        const uint4* hv = reinterpret_cast<const uint4*>(hh[SLOT]);          \
        _Pragma("unroll")                                                    \
        for (int q = 0; q < 4; q++) {                                        \
            const uint4 v = hv[q];                                           \
            const __half2 h0 = *reinterpret_cast<const __half2*>(&v.x);      \
            const __half2 h1 = *reinterpret_cast<const __half2*>(&v.y);      \
            const __half2 h2 = *reinterpret_cast<const __half2*>(&v.z);      \
            const __half2 h3 = *reinterpret_cast<const __half2*>(&v.w);      \
            accr2  = __hfma2(wr16[4 * q + 0], h0, accr2);                    \
            accz2  = __hfma2(wz16[4 * q + 0], h0, accz2);                    \
            acca2a = __hfma2(wa16[4 * q + 0], h0, acca2a);                   \
            accr2  = __hfma2(wr16[4 * q + 1], h1, accr2);                    \
            accz2  = __hfma2(wz16[4 * q + 1], h1, accz2);                    \
            acca2b = __hfma2(wa16[4 * q + 1], h1, acca2b);                   \
            accr2  = __hfma2(wr16[4 * q + 2], h2, accr2);                    \
            accz2  = __hfma2(wz16[4 * q + 2], h2, accz2);                    \
            acca2a = __hfma2(wa16[4 * q + 2], h2, acca2a);                   \
            accr2  = __hfma2(wr16[4 * q + 3], h3, accr2);                    \
            accz2  = __hfma2(wz16[4 * q + 3], h3, accz2);                    \
            acca2b = __hfma2(wa16[4 * q + 3], h3, acca2b);                   \
        }                                                                    \
        const float2 frh = __half22float2(accr2);                            \
        const float2 fzh = __half22float2(accz2);                            \
        const float2 faa = __half22float2(acca2a);                           \
        const float2 fab = __half22float2(acca2b);                           \
        const float ha = (faa.x + faa.y) + (fab.x + fab.y);                  \
        const float r = fmaf(0.5f, tanh_hw(frh.x + frh.y), 0.5f);            \
        const float z = fmaf(0.5f, tanh_hw(fzh.x + fzh.y), 0.5f);            \
        const float n = tanh_hw(fmaf(r, ha, ia));                            \
        h = fmaf(z, h - n, n);                                               \
        if (j == 0) gp[GOFF] = h;                                            \
    }

    float* gp = gout;
    for (int t0 = 0; t0 < TT; t0 += 32) {
        __syncwarp();               // previous chunk's x readers done
        // fp32 xbuf (a-gate) + fp16 transposed planes (r/z gates).
        xbuf[j]      = p0;
        xbuf[32 + j] = p1;
        xbuf[64 + j] = p2;
        {
            const int i0 = j, i1 = 32 + j, i2 = 64 + j;
            xh[i0 % 3][i0 / 3] = __float2half(p0);
            xh[i1 % 3][i1 / 3] = __float2half(p1);
            xh[i2 % 3][i2 / 3] = __float2half(p2);
        }
        if (t0 + 32 < TT) {         // prefetch next chunk (hidden over 32 steps)
            const float* nx = gx + (t0 + 32) * 3;
            p0 = nx[j];
            p1 = nx[32 + j];
            p2 = nx[64 + j];
        }

        const __half2* xh0 = reinterpret_cast<const __half2*>(xh[0]);
        const __half2* xh1 = reinterpret_cast<const __half2*>(xh[1]);
        const __half2* xh2 = reinterpret_cast<const __half2*>(xh[2]);

#pragma unroll 4
        for (int s2 = 0; s2 < 16; s2++) {
            // Paired r/z input gates for steps (2*s2, 2*s2+1): 3 HFMA2 each.
            // NOTE: first read of xh happens after the __syncwarp inside
            // GRU_STEP would be too late for step 0 publication ordering —
            // but xh was written before the chunk-top __syncwarp for s2==0
            // and is read-only within the chunk, so reading here is safe.
            const __half2 xp0 = xh0[s2];
            const __half2 xp1 = xh1[s2];
            const __half2 xp2 = xh2[s2];
            const __half2 igrh =
                __hfma2(wirh[2], xp2, __hfma2(wirh[1], xp1, __hfma2(wirh[0], xp0, brh2)));
            const __half2 igzh =
                __hfma2(wizh[2], xp2, __hfma2(wizh[1], xp1, __hfma2(wizh[0], xp0, bzh2)));
            const int xo = s2 * 6;
            GRU_STEP(0, xo,     0, __low2half(igrh),  __low2half(igzh))
            GRU_STEP(1, xo + 3, 1, __high2half(igrh), __high2half(igzh))
            gp += 2;
        }
    }
#undef GRU_STEP
}

extern "C" void kernel_launch(void* const* d_in, const int* in_sizes, int n_in,
                              void* d_out, int out_size) {
    const float* inp    = (const float*)d_in[0];
    const float* w_ih   = (const float*)d_in[1];
    const float* w_hh   = (const float*)d_in[2];
    const float* bias   = (const float*)d_in[3];
    const float* bias_n = (const float*)d_in[4];
    float* out = (float*)d_out;
    gru_warp_kernel<<<BB, 32>>>(inp, w_ih, w_hh, bias, bias_n, out);
}

// round 16
// speedup vs baseline: 1.0506x; 1.0506x over previous
#include <cuda_runtime.h>
#include <cuda_fp16.h>
#include <cstdint>

// Shape: inp:[2048,2048,3] f32, w_ih:[96,3], w_hh:[96,32], bias:[96], bias_n:[32]
// out:[2048,2048,1] f32 (h[0] each step)
#define TT 2048
#define BB 2048

__device__ __forceinline__ float tanh_hw(float x) {
    float y; asm("tanh.approx.f32 %0, %1;" : "=f"(y) : "f"(x));
    return y;
}

// Compiler-only ordering fence. The warp is fully convergent and a warp's
// shared-memory ops drain through the MIO queue in program order, so its own
// STS is visible to its own later LDS across lanes WITHOUT a barrier. The
// only reordering hazard is the compiler; this stops it. Removes the ~23-cyc
// WARPSYNC from all 2048 serial steps.
#define WARP_FENCE() asm volatile("" ::: "memory")

// One warp per sequence; lane j owns hidden unit j. (R14 structure, banked
// best at 680us, minus the per-step __syncwarp.) All three hidden matvecs are
// HFMA2 (rt 2, 1 cyc/MAC); carried h stays fp32 in registers so the
// recurrence is exact — only the lane->lane broadcast is fp16. The a-gate
// uses two interleaved accumulators to halve its rounding chain. r/z weights
// pre-scaled by 0.5 so sigmoid = FFMA-imm(0.5, MUFU.TANH(sum), 0.5).
// 2-step unrolled loop, compile-time hbuf slots, pointer-carry output.
__global__ void __launch_bounds__(32, 14)
gru_warp_kernel(const float* __restrict__ inp,
                const float* __restrict__ w_ih,
                const float* __restrict__ w_hh,
                const float* __restrict__ bias,
                const float* __restrict__ bias_n,
                float* __restrict__ out) {
    __shared__ __align__(16) __half hh[2][32];   // fp16 h broadcast buffer
    __shared__ float xbuf[96];                   // 32 timesteps of x

    const int j = threadIdx.x;
    const int b = blockIdx.x;

    // ---- W_hh rows as f16x2 pairs; r/z rows PRE-SCALED by 0.5 ----
    __half2 wr16[16], wz16[16], wa16[16];
    {
        const float* rr = w_hh + (0 * 32 + j) * 32;
        const float* rz = w_hh + (1 * 32 + j) * 32;
        const float* ra = w_hh + (2 * 32 + j) * 32;
#pragma unroll
        for (int k = 0; k < 16; k++) {
            wr16[k] = __floats2half2_rn(0.5f * rr[2 * k], 0.5f * rr[2 * k + 1]);
            wz16[k] = __floats2half2_rn(0.5f * rz[2 * k], 0.5f * rz[2 * k + 1]);
            wa16[k] = __floats2half2_rn(ra[2 * k], ra[2 * k + 1]);
        }
    }
    // W_ih rows: r/z pre-scaled by 0.5; a row unscaled.
    const float wir0 = 0.5f * w_ih[(0 * 32 + j) * 3 + 0];
    const float wir1 = 0.5f * w_ih[(0 * 32 + j) * 3 + 1];
    const float wir2 = 0.5f * w_ih[(0 * 32 + j) * 3 + 2];
    const float wiz0 = 0.5f * w_ih[(1 * 32 + j) * 3 + 0];
    const float wiz1 = 0.5f * w_ih[(1 * 32 + j) * 3 + 1];
    const float wiz2 = 0.5f * w_ih[(1 * 32 + j) * 3 + 2];
    const float wia0 = w_ih[(2 * 32 + j) * 3 + 0];
    const float wia1 = w_ih[(2 * 32 + j) * 3 + 1];
    const float wia2 = w_ih[(2 * 32 + j) * 3 + 2];
    const float br  = 0.5f * bias[0 * 32 + j];
    const float bz  = 0.5f * bias[1 * 32 + j];
    const float ban = bias[2 * 32 + j] + bias_n[j];

    float h = 0.0f;
    const float* gx   = inp + (size_t)b * (TT * 3);
    float*       gout = out + (size_t)b * TT;

    float p0 = gx[j], p1 = gx[32 + j], p2 = gx[64 + j];

#define GRU_STEP(SLOT, XO, GOFF)                                             \
    {                                                                        \
        hh[SLOT][j] = __float2half(h);                                       \
        WARP_FENCE();                                                        \
        const float x0 = xbuf[(XO) + 0];                                     \
        const float x1 = xbuf[(XO) + 1];                                     \
        const float x2 = xbuf[(XO) + 2];                                     \
        const float ir = fmaf(wir2, x2, fmaf(wir1, x1, fmaf(wir0, x0, br))); \
        const float iz = fmaf(wiz2, x2, fmaf(wiz1, x1, fmaf(wiz0, x0, bz))); \
        const float ia = fmaf(wia2, x2, fmaf(wia1, x1, fmaf(wia0, x0, ban))); \
        /* three matvecs, all HFMA2 over 4 broadcast LDS.128 */              \
        __half2 accr2 = __float2half2_rn(0.0f);                              \
        __half2 accz2 = __float2half2_rn(0.0f);                              \
        __half2 acca2a = __float2half2_rn(0.0f);   /* dual accumulators */   \
        __half2 acca2b = __float2half2_rn(0.0f);   /* halve rounding chain */\
        const uint4* hv = reinterpret_cast<const uint4*>(hh[SLOT]);          \
        _Pragma("unroll")                                                    \
        for (int q = 0; q < 4; q++) {                                        \
            const uint4 v = hv[q];                                           \
            const __half2 h0 = *reinterpret_cast<const __half2*>(&v.x);      \
            const __half2 h1 = *reinterpret_cast<const __half2*>(&v.y);      \
            const __half2 h2 = *reinterpret_cast<const __half2*>(&v.z);      \
            const __half2 h3 = *reinterpret_cast<const __half2*>(&v.w);      \
            accr2  = __hfma2(wr16[4 * q + 0], h0, accr2);                    \
            accz2  = __hfma2(wz16[4 * q + 0], h0, accz2);                    \
            acca2a = __hfma2(wa16[4 * q + 0], h0, acca2a);                   \
            accr2  = __hfma2(wr16[4 * q + 1], h1, accr2);                    \
            accz2  = __hfma2(wz16[4 * q + 1], h1, accz2);                    \
            acca2b = __hfma2(wa16[4 * q + 1], h1, acca2b);                   \
            accr2  = __hfma2(wr16[4 * q + 2], h2, accr2);                    \
            accz2  = __hfma2(wz16[4 * q + 2], h2, accz2);                    \
            acca2a = __hfma2(wa16[4 * q + 2], h2, acca2a);                   \
            accr2  = __hfma2(wr16[4 * q + 3], h3, accr2);                    \
            accz2  = __hfma2(wz16[4 * q + 3], h3, accz2);                    \
            acca2b = __hfma2(wa16[4 * q + 3], h3, acca2b);                   \
        }                                                                    \
        const float2 frh = __half22float2(accr2);                            \
        const float2 fzh = __half22float2(accz2);                            \
        const float2 faa = __half22float2(acca2a);                           \
        const float2 fab = __half22float2(acca2b);                           \
        const float ha = (faa.x + faa.y) + (fab.x + fab.y);                  \
        /* pre-scaled sums: sigma = 0.5 + 0.5*tanh(halfsum) */               \
        const float r = fmaf(0.5f, tanh_hw(ir + (frh.x + frh.y)), 0.5f);     \
        const float z = fmaf(0.5f, tanh_hw(iz + (fzh.x + fzh.y)), 0.5f);     \
        const float n = tanh_hw(fmaf(r, ha, ia));                            \
        h = fmaf(z, h - n, n);                                               \
        if (j == 0) gp[GOFF] = h;                                            \
    }

    float* gp = gout;
    for (int t0 = 0; t0 < TT; t0 += 32) {
        WARP_FENCE();               // order xbuf rewrite after last readers
        xbuf[j]      = p0;
        xbuf[32 + j] = p1;
        xbuf[64 + j] = p2;
        if (t0 + 32 < TT) {         // prefetch next chunk (hidden over 32 steps)
            const float* nx = gx + (t0 + 32) * 3;
            p0 = nx[j];
            p1 = nx[32 + j];
            p2 = nx[64 + j];
        }
#pragma unroll 4
        for (int xo = 0; xo < 96; xo += 6) {
            GRU_STEP(0, xo, 0)
            GRU_STEP(1, xo + 3, 1)
            gp += 2;
        }
    }
#undef GRU_STEP
}

extern "C" void kernel_launch(void* const* d_in, const int* in_sizes, int n_in,
                              void* d_out, int out_size) {
    const float* inp    = (const float*)d_in[0];
    const float* w_ih   = (const float*)d_in[1];
    const float* w_hh   = (const float*)d_in[2];
    const float* bias   = (const float*)d_in[3];
    const float* bias_n = (const float*)d_in[4];
    float* out = (float*)d_out;
    gru_warp_kernel<<<BB, 32>>>(inp, w_ih, w_hh, bias, bias_n, out);
}

// round 17
// speedup vs baseline: 1.1004x; 1.0474x over previous
#include <cuda_runtime.h>
#include <cuda_fp16.h>
#include <cstdint>

// Shape: inp:[2048,2048,3] f32, w_ih:[96,3], w_hh:[96,32], bias:[96], bias_n:[32]
// out:[2048,2048,1] f32 (h[0] each step)
#define TT 2048
#define BB 2048

__device__ __forceinline__ float tanh_hw(float x) {
    float y; asm("tanh.approx.f32 %0, %1;" : "=f"(y) : "f"(x));
    return y;
}

// Compiler-only ordering fence (validated R16: warp-convergent smem STS->LDS
// needs no hardware barrier, only protection from compiler reordering).
#define WARP_FENCE() asm volatile("" ::: "memory")

// One warp per sequence; lane j owns hidden unit j.
// Model (calibrated R12-R16): time = 4 warps x fma-pipe-cyc/step on the
// binding SMSPs. All three hidden matvecs are HFMA2 (96 cyc). This round the
// accumulator reductions happen IN fp16: hadd2(acc, swapped(acc)) — the swap
// is PRMT (alu pipe, free) — then one F2F per gate, replacing the four
// half22float2 unpack pairs + fp32 cross-adds (~28 cyc -> ~14). ig addition,
// all tanh evaluations and the h update remain fp32; carried h is fp32 in
// registers so the recurrence stays exact. r/z weights pre-scaled by 0.5
// (sigmoid fold). 2-step unrolled loop, compile-time hbuf slots,
// pointer-carry output addressing.
__global__ void __launch_bounds__(32, 14)
gru_warp_kernel(const float* __restrict__ inp,
                const float* __restrict__ w_ih,
                const float* __restrict__ w_hh,
                const float* __restrict__ bias,
                const float* __restrict__ bias_n,
                float* __restrict__ out) {
    __shared__ __align__(16) __half hh[2][32];   // fp16 h broadcast buffer
    __shared__ float xbuf[96];                   // 32 timesteps of x

    const int j = threadIdx.x;
    const int b = blockIdx.x;

    // ---- W_hh rows as f16x2 pairs; r/z rows PRE-SCALED by 0.5 ----
    __half2 wr16[16], wz16[16], wa16[16];
    {
        const float* rr = w_hh + (0 * 32 + j) * 32;
        const float* rz = w_hh + (1 * 32 + j) * 32;
        const float* ra = w_hh + (2 * 32 + j) * 32;
#pragma unroll
        for (int k = 0; k < 16; k++) {
            wr16[k] = __floats2half2_rn(0.5f * rr[2 * k], 0.5f * rr[2 * k + 1]);
            wz16[k] = __floats2half2_rn(0.5f * rz[2 * k], 0.5f * rz[2 * k + 1]);
            wa16[k] = __floats2half2_rn(ra[2 * k], ra[2 * k + 1]);
        }
    }
    // W_ih rows: r/z pre-scaled by 0.5; a row unscaled.
    const float wir0 = 0.5f * w_ih[(0 * 32 + j) * 3 + 0];
    const float wir1 = 0.5f * w_ih[(0 * 32 + j) * 3 + 1];
    const float wir2 = 0.5f * w_ih[(0 * 32 + j) * 3 + 2];
    const float wiz0 = 0.5f * w_ih[(1 * 32 + j) * 3 + 0];
    const float wiz1 = 0.5f * w_ih[(1 * 32 + j) * 3 + 1];
    const float wiz2 = 0.5f * w_ih[(1 * 32 + j) * 3 + 2];
    const float wia0 = w_ih[(2 * 32 + j) * 3 + 0];
    const float wia1 = w_ih[(2 * 32 + j) * 3 + 1];
    const float wia2 = w_ih[(2 * 32 + j) * 3 + 2];
    const float br  = 0.5f * bias[0 * 32 + j];
    const float bz  = 0.5f * bias[1 * 32 + j];
    const float ban = bias[2 * 32 + j] + bias_n[j];

    float h = 0.0f;
    const float* gx   = inp + (size_t)b * (TT * 3);
    float*       gout = out + (size_t)b * TT;

    float p0 = gx[j], p1 = gx[32 + j], p2 = gx[64 + j];

#define GRU_STEP(SLOT, XO, GOFF)                                             \
    {                                                                        \
        hh[SLOT][j] = __float2half(h);                                       \
        WARP_FENCE();                                                        \
        const float x0 = xbuf[(XO) + 0];                                     \
        const float x1 = xbuf[(XO) + 1];                                     \
        const float x2 = xbuf[(XO) + 2];                                     \
        const float ir = fmaf(wir2, x2, fmaf(wir1, x1, fmaf(wir0, x0, br))); \
        const float iz = fmaf(wiz2, x2, fmaf(wiz1, x1, fmaf(wiz0, x0, bz))); \
        const float ia = fmaf(wia2, x2, fmaf(wia1, x1, fmaf(wia0, x0, ban))); \
        /* three matvecs, all HFMA2 over 4 broadcast LDS.128 */              \
        __half2 accr2 = __float2half2_rn(0.0f);                              \
        __half2 accz2 = __float2half2_rn(0.0f);                              \
        __half2 acca2a = __float2half2_rn(0.0f);   /* dual accumulators */   \
        __half2 acca2b = __float2half2_rn(0.0f);   /* halve rounding chain */\
        const uint4* hv = reinterpret_cast<const uint4*>(hh[SLOT]);          \
        _Pragma("unroll")                                                    \
        for (int q = 0; q < 4; q++) {                                        \
            const uint4 v = hv[q];                                           \
            const __half2 h0 = *reinterpret_cast<const __half2*>(&v.x);      \
            const __half2 h1 = *reinterpret_cast<const __half2*>(&v.y);      \
            const __half2 h2 = *reinterpret_cast<const __half2*>(&v.z);      \
            const __half2 h3 = *reinterpret_cast<const __half2*>(&v.w);      \
            accr2  = __hfma2(wr16[4 * q + 0], h0, accr2);                    \
            accz2  = __hfma2(wz16[4 * q + 0], h0, accz2);                    \
            acca2a = __hfma2(wa16[4 * q + 0], h0, acca2a);                   \
            accr2  = __hfma2(wr16[4 * q + 1], h1, accr2);                    \
            accz2  = __hfma2(wz16[4 * q + 1], h1, accz2);                    \
            acca2b = __hfma2(wa16[4 * q + 1], h1, acca2b);                   \
            accr2  = __hfma2(wr16[4 * q + 2], h2, accr2);                    \
            accz2  = __hfma2(wz16[4 * q + 2], h2, accz2);                    \
            acca2a = __hfma2(wa16[4 * q + 2], h2, acca2a);                   \
            accr2  = __hfma2(wr16[4 * q + 3], h3, accr2);                    \
            accz2  = __hfma2(wz16[4 * q + 3], h3, accz2);                    \
            acca2b = __hfma2(wa16[4 * q + 3], h3, acca2b);                   \
        }                                                                    \
        /* in-fp16 reductions: hadd2 with PRMT-swapped halves (PRMT=alu) */  \
        const __half2 rsum = __hadd2(accr2, __lowhigh2highlow(accr2));       \
        const __half2 zsum = __hadd2(accz2, __lowhigh2highlow(accz2));       \
        __half2 asum = __hadd2(acca2a, acca2b);                              \
        asum = __hadd2(asum, __lowhigh2highlow(asum));                       \
        const float rs = __low2float(rsum);                                  \
        const float zs = __low2float(zsum);                                  \
        const float ha = __low2float(asum);                                  \
        /* pre-scaled sums: sigma = 0.5 + 0.5*tanh(halfsum) */               \
        const float r = fmaf(0.5f, tanh_hw(ir + rs), 0.5f);                  \
        const float z = fmaf(0.5f, tanh_hw(iz + zs), 0.5f);                  \
        const float n = tanh_hw(fmaf(r, ha, ia));                            \
        h = fmaf(z, h - n, n);                                               \
        if (j == 0) gp[GOFF] = h;                                            \
    }

    float* gp = gout;
    for (int t0 = 0; t0 < TT; t0 += 32) {
        WARP_FENCE();               // order xbuf rewrite after last readers
        xbuf[j]      = p0;
        xbuf[32 + j] = p1;
        xbuf[64 + j] = p2;
        if (t0 + 32 < TT) {         // prefetch next chunk (hidden over 32 steps)
            const float* nx = gx + (t0 + 32) * 3;
            p0 = nx[j];
            p1 = nx[32 + j];
            p2 = nx[64 + j];
        }
#pragma unroll 4
        for (int xo = 0; xo < 96; xo += 6) {
            GRU_STEP(0, xo, 0)
            GRU_STEP(1, xo + 3, 1)
            gp += 2;
        }
    }
#undef GRU_STEP
}

extern "C" void kernel_launch(void* const* d_in, const int* in_sizes, int n_in,
                              void* d_out, int out_size) {
    const float* inp    = (const float*)d_in[0];
    const float* w_ih   = (const float*)d_in[1];
    const float* w_hh   = (const float*)d_in[2];
    const float* bias   = (const float*)d_in[3];
    const float* bias_n = (const float*)d_in[4];
    float* out = (float*)d_out;
    gru_warp_kernel<<<BB, 32>>>(inp, w_ih, w_hh, bias, bias_n, out);
}